// round 13
// baseline (speedup 1.0000x reference)
#include <cuda_runtime.h>
#include <math.h>

#define NN 100000
#define EE 1600000
#define HH 64
#define KK 32
#define INCH 161   // 1 + 96 + 64

// ---------------- scratch (device globals) -------------------------------------
__device__ __align__(16) float g_xin [NN * HH];
__device__ __align__(16) float g_outf[NN * HH];
__device__ __align__(16) float g_outb[NN * HH];
__device__ __align__(16) float g_degf[NN];        // reciprocal after k_rdeg
__device__ __align__(16) float g_degb[NN];

// ---------------- packed f32x2 helpers -----------------------------------------
typedef unsigned long long ull;
static __device__ __forceinline__ ull pack2(float lo, float hi) {
    ull r;
    asm("mov.b64 %0, {%1, %2};" : "=l"(r) : "f"(lo), "f"(hi));
    return r;
}
static __device__ __forceinline__ void unpack2(ull v, float& lo, float& hi) {
    asm("mov.b64 {%0, %1}, %2;" : "=f"(lo), "=f"(hi) : "l"(v));
}
static __device__ __forceinline__ void fma2(ull& d, ull a, ull b) {
    asm("fma.rn.f32x2 %0, %1, %2, %0;" : "+l"(d) : "l"(a), "l"(b));
}
static __device__ __forceinline__ void red_add_v4(float* ptr, float a, float b,
                                                  float c, float d) {
    asm volatile("red.global.add.v4.f32 [%0], {%1, %2, %3, %4};"
                 :: "l"(ptr), "f"(a), "f"(b), "f"(c), "f"(d) : "memory");
}

// ---- 4 nodes x 16 outputs: one k-step. Wr = 16-col slice (warp-uniform). ----
// 4 LDS.128 feed 32 fma2  ->  L1-op:fma2 ratio 1:8.
static __device__ __forceinline__ void step4(ull* a0, ull* a1, ull* a2, ull* a3,
                                             const float* Wr,
                                             float x0, float x1, float x2, float x3) {
    const ulonglong2* w = (const ulonglong2*)Wr;
    ulonglong2 w0 = w[0], w1 = w[1], w2 = w[2], w3 = w[3];
    ull A0 = pack2(x0, x0), A1 = pack2(x1, x1);
    ull A2 = pack2(x2, x2), A3 = pack2(x3, x3);
    fma2(a0[0], A0, w0.x); fma2(a0[1], A0, w0.y);
    fma2(a0[2], A0, w1.x); fma2(a0[3], A0, w1.y);
    fma2(a0[4], A0, w2.x); fma2(a0[5], A0, w2.y);
    fma2(a0[6], A0, w3.x); fma2(a0[7], A0, w3.y);
    fma2(a1[0], A1, w0.x); fma2(a1[1], A1, w0.y);
    fma2(a1[2], A1, w1.x); fma2(a1[3], A1, w1.y);
    fma2(a1[4], A1, w2.x); fma2(a1[5], A1, w2.y);
    fma2(a1[6], A1, w3.x); fma2(a1[7], A1, w3.y);
    fma2(a2[0], A2, w0.x); fma2(a2[1], A2, w0.y);
    fma2(a2[2], A2, w1.x); fma2(a2[3], A2, w1.y);
    fma2(a2[4], A2, w2.x); fma2(a2[5], A2, w2.y);
    fma2(a2[6], A2, w3.x); fma2(a2[7], A2, w3.y);
    fma2(a3[0], A3, w0.x); fma2(a3[1], A3, w0.y);
    fma2(a3[2], A3, w1.x); fma2(a3[3], A3, w1.y);
    fma2(a3[4], A3, w2.x); fma2(a3[5], A3, w2.y);
    fma2(a3[6], A3, w3.x); fma2(a3[7], A3, w3.y);
}

static __device__ __forceinline__ void init16(ull* acc, const float* bias16) {
    const float2* b = (const float2*)bias16;
#pragma unroll
    for (int j = 0; j < 8; j++) {
        float2 v = b[j];
        acc[j] = pack2(v.x, v.y);
    }
}

static __device__ __forceinline__ void store16(float* dst, const ull* acc) {
#pragma unroll
    for (int j = 0; j < 4; j++) {
        float l0, h0, l1, h1;
        unpack2(acc[2 * j], l0, h0);
        unpack2(acc[2 * j + 1], l1, h1);
        ((float4*)dst)[j] = make_float4(l0, h0, l1, h1);
    }
}

// ---- 2 nodes x 32 outputs (kept for k_heads2) ----
static __device__ __forceinline__ void step2(ull* acc0, ull* acc1,
                                             const float* Wr, float a0, float a1) {
    const ulonglong2* w = (const ulonglong2*)Wr;
    ull A0 = pack2(a0, a0), A1 = pack2(a1, a1);
#pragma unroll
    for (int j = 0; j < 8; j++) {
        ulonglong2 wv = w[j];
        fma2(acc0[2 * j], A0, wv.x); fma2(acc0[2 * j + 1], A0, wv.y);
        fma2(acc1[2 * j], A1, wv.x); fma2(acc1[2 * j + 1], A1, wv.y);
    }
}
static __device__ __forceinline__ void init_acc(ull* acc0, ull* acc1,
                                                const float* bias32) {
    const ulonglong2* bb = (const ulonglong2*)bias32;
#pragma unroll
    for (int j = 0; j < 8; j++) {
        ulonglong2 b = bb[j];
        acc0[2 * j] = b.x; acc0[2 * j + 1] = b.y;
        acc1[2 * j] = b.x; acc1[2 * j + 1] = b.y;
    }
}

// ---------------- k0: zero degree arrays only -----------------------------------
__global__ void k_zero() {
    int i = blockIdx.x * blockDim.x + threadIdx.x;
    if (i < NN / 4) {
        float4 z = make_float4(0.f, 0.f, 0.f, 0.f);
        reinterpret_cast<float4*>(g_degf)[i] = z;
        reinterpret_cast<float4*>(g_degb)[i] = z;
    }
}

// ---------------- k1: weighted degrees -----------------------------------------
__global__ void k_deg(const int* __restrict__ ei, const float* __restrict__ ew) {
    int e = blockIdx.x * blockDim.x + threadIdx.x;
    if (e >= EE) return;
    int   s = ei[e];
    int   t = ei[EE + e];
    float w = ew[e];
    if (s == t || w == 0.f) return;
    atomicAdd(&g_degf[t], w);
    atomicAdd(&g_degb[s], w);
}

__global__ void k_rdeg() {
    int n = blockIdx.x * blockDim.x + threadIdx.x;
    if (n >= NN) return;
    float df = g_degf[n];
    float db = g_degb[n];
    g_degf[n] = (df > 0.f) ? (1.0f / df) : 1.0f;
    g_degb[n] = (db > 0.f) ? (1.0f / db) : 1.0f;
}

// ---------------- k2: input projection (4 nodes x 16 outs / thread) ------------
// warp w: r = w&3 (16-col W slice, warp-uniform), wp = w>>2.
// Nodes: n_i = blk*256 + wp*128 + 32*i + l. Epilogue zeroes outf/outb slice.
__global__ __launch_bounds__(256, 2) void k_proj4(const float* __restrict__ x,
                                                  const float* __restrict__ xh,
                                                  const float* __restrict__ h,
                                                  const float* __restrict__ Win,
                                                  const float* __restrict__ bin) {
    __shared__ __align__(16) float Ws[INCH * HH];   // 41216 B
    int tid = threadIdx.x;
    for (int i = tid; i < INCH * HH; i += 256) Ws[i] = Win[i];
    __syncthreads();

    int w = tid >> 5, l = tid & 31;
    int r  = w & 3;
    int wp = w >> 2;
    int nb = blockIdx.x * 256 + wp * 128 + l;
    int n0 = nb, n1 = nb + 32, n2 = nb + 64, n3 = nb + 96;
    int m0 = min(n0, NN - 1), m1 = min(n1, NN - 1);
    int m2 = min(n2, NN - 1), m3 = min(n3, NN - 1);

    ull a0[8], a1[8], a2[8], a3[8];
    init16(a0, bin + 16 * r); init16(a1, bin + 16 * r);
    init16(a2, bin + 16 * r); init16(a3, bin + 16 * r);
    const float* W = Ws + 16 * r;

    // k = 0 : x
    step4(a0, a1, a2, a3, W, x[m0], x[m1], x[m2], x[m3]);

    // k = 1..96 : x_hat_1
    const float4* X0 = (const float4*)(xh + (size_t)m0 * 96);
    const float4* X1 = (const float4*)(xh + (size_t)m1 * 96);
    const float4* X2 = (const float4*)(xh + (size_t)m2 * 96);
    const float4* X3 = (const float4*)(xh + (size_t)m3 * 96);
    for (int kk = 0; kk < 24; kk++) {
        float4 v0 = X0[kk], v1 = X1[kk], v2 = X2[kk], v3 = X3[kk];
        const float* Wk = W + (1 + 4 * kk) * HH;
        step4(a0, a1, a2, a3, Wk,          v0.x, v1.x, v2.x, v3.x);
        step4(a0, a1, a2, a3, Wk + HH,     v0.y, v1.y, v2.y, v3.y);
        step4(a0, a1, a2, a3, Wk + 2 * HH, v0.z, v1.z, v2.z, v3.z);
        step4(a0, a1, a2, a3, Wk + 3 * HH, v0.w, v1.w, v2.w, v3.w);
    }
    // k = 97..160 : h
    const float4* H0 = (const float4*)(h + (size_t)m0 * 64);
    const float4* H1 = (const float4*)(h + (size_t)m1 * 64);
    const float4* H2 = (const float4*)(h + (size_t)m2 * 64);
    const float4* H3 = (const float4*)(h + (size_t)m3 * 64);
    for (int kk = 0; kk < 16; kk++) {
        float4 v0 = H0[kk], v1 = H1[kk], v2 = H2[kk], v3 = H3[kk];
        const float* Wk = W + (97 + 4 * kk) * HH;
        step4(a0, a1, a2, a3, Wk,          v0.x, v1.x, v2.x, v3.x);
        step4(a0, a1, a2, a3, Wk + HH,     v0.y, v1.y, v2.y, v3.y);
        step4(a0, a1, a2, a3, Wk + 2 * HH, v0.z, v1.z, v2.z, v3.z);
        step4(a0, a1, a2, a3, Wk + 3 * HH, v0.w, v1.w, v2.w, v3.w);
    }

    float4 z = make_float4(0.f, 0.f, 0.f, 0.f);
#pragma unroll
    for (int i = 0; i < 4; i++) {
        int gn = nb + 32 * i;
        if (gn >= NN) continue;
        const ull* acc = (i == 0) ? a0 : (i == 1) ? a1 : (i == 2) ? a2 : a3;
        store16(g_xin + (size_t)gn * 64 + 16 * r, acc);
        float4* zf = (float4*)(g_outf + (size_t)gn * 64 + 16 * r);
        float4* zb = (float4*)(g_outb + (size_t)gn * 64 + 16 * r);
#pragma unroll
        for (int j = 0; j < 4; j++) { zf[j] = z; zb[j] = z; }
    }
}

// ---------------- k3: edge diffusion scatter -----------------------------------
__global__ void k_diff(const int* __restrict__ ei, const float* __restrict__ ew) {
    int idx = blockIdx.x * blockDim.x + threadIdx.x;
    int e = idx >> 4;
    int c = idx & 15;
    if (e >= EE) return;
    int   s = ei[e];
    int   t = ei[EE + e];
    float w = ew[e];
    if (s == t || w == 0.f) return;
    float wf = w * g_degf[t];
    float wb = w * g_degb[s];

    const float4* xin4 = reinterpret_cast<const float4*>(g_xin);
    float4 a = xin4[(size_t)s * 16 + c];
    red_add_v4(g_outf + (size_t)t * 64 + c * 4,
               wf * a.x, wf * a.y, wf * a.z, wf * a.w);

    float4 b = xin4[(size_t)t * 16 + c];
    red_add_v4(g_outb + (size_t)s * 64 + c * 4,
               wb * b.x, wb * b.y, wb * b.z, wb * b.w);
}

// ---------------- k4: filter GEMM (4 nodes x 16 outs) + out1/h epilogue --------
__global__ __launch_bounds__(256, 2) void k_filt4(const float* __restrict__ h,
                                                  const float* __restrict__ Wf,
                                                  const float* __restrict__ bf,
                                                  float* __restrict__ out1,
                                                  float* __restrict__ hout) {
    __shared__ __align__(16) float Ws[128 * HH];    // 32 KB
    int tid = threadIdx.x;
    for (int i = tid; i < 128 * HH; i += 256) Ws[i] = Wf[i];
    __syncthreads();

    int w = tid >> 5, l = tid & 31;
    int r  = w & 3;
    int wp = w >> 2;
    int nb = blockIdx.x * 256 + wp * 128 + l;
    int n0 = nb, n1 = nb + 32, n2 = nb + 64, n3 = nb + 96;
    int m0 = min(n0, NN - 1), m1 = min(n1, NN - 1);
    int m2 = min(n2, NN - 1), m3 = min(n3, NN - 1);

    ull a0[8], a1[8], a2[8], a3[8];
    init16(a0, bf + 16 * r); init16(a1, bf + 16 * r);
    init16(a2, bf + 16 * r); init16(a3, bf + 16 * r);
    const float* W = Ws + 16 * r;

    const float4* F0 = (const float4*)(g_outf + (size_t)m0 * 64);
    const float4* F1 = (const float4*)(g_outf + (size_t)m1 * 64);
    const float4* F2 = (const float4*)(g_outf + (size_t)m2 * 64);
    const float4* F3 = (const float4*)(g_outf + (size_t)m3 * 64);
    for (int kk = 0; kk < 16; kk++) {
        float4 v0 = F0[kk], v1 = F1[kk], v2 = F2[kk], v3 = F3[kk];
        const float* Wk = W + (4 * kk) * HH;
        step4(a0, a1, a2, a3, Wk,          v0.x, v1.x, v2.x, v3.x);
        step4(a0, a1, a2, a3, Wk + HH,     v0.y, v1.y, v2.y, v3.y);
        step4(a0, a1, a2, a3, Wk + 2 * HH, v0.z, v1.z, v2.z, v3.z);
        step4(a0, a1, a2, a3, Wk + 3 * HH, v0.w, v1.w, v2.w, v3.w);
    }
    const float4* B0 = (const float4*)(g_outb + (size_t)m0 * 64);
    const float4* B1 = (const float4*)(g_outb + (size_t)m1 * 64);
    const float4* B2 = (const float4*)(g_outb + (size_t)m2 * 64);
    const float4* B3 = (const float4*)(g_outb + (size_t)m3 * 64);
    for (int kk = 0; kk < 16; kk++) {
        float4 v0 = B0[kk], v1 = B1[kk], v2 = B2[kk], v3 = B3[kk];
        const float* Wk = W + (64 + 4 * kk) * HH;
        step4(a0, a1, a2, a3, Wk,          v0.x, v1.x, v2.x, v3.x);
        step4(a0, a1, a2, a3, Wk + HH,     v0.y, v1.y, v2.y, v3.y);
        step4(a0, a1, a2, a3, Wk + 2 * HH, v0.z, v1.z, v2.z, v3.z);
        step4(a0, a1, a2, a3, Wk + 3 * HH, v0.w, v1.w, v2.w, v3.w);
    }

#pragma unroll
    for (int i = 0; i < 4; i++) {
        int gn = nb + 32 * i;
        if (gn >= NN) continue;
        const ull* acc = (i == 0) ? a0 : (i == 1) ? a1 : (i == 2) ? a2 : a3;
        store16(out1 + (size_t)gn * 128 + 16 * r, acc);
        // h passthrough for this 16-col slice
        const float4* hp = (const float4*)(h + (size_t)gn * 64 + 16 * r);
        float4* o2 = (float4*)(out1 + (size_t)gn * 128 + 64 + 16 * r);
        float4* ho = (float4*)(hout + (size_t)gn * 64 + 16 * r);
#pragma unroll
        for (int j = 0; j < 4; j++) { float4 v = hp[j]; o2[j] = v; ho[j] = v; }
    }
}

// ---------------- k5: fused GMM heads (2 nodes x one 32-wide head / thread) ----
// 384 threads: r = tid>>7 (0=mu,1=sigma,2=pi; warp-uniform), p = tid&127.
__global__ __launch_bounds__(384, 1) void k_heads2(const float* __restrict__ out1,
                                                   const float* __restrict__ Wm,
                                                   const float* __restrict__ bm,
                                                   const float* __restrict__ Wsg,
                                                   const float* __restrict__ bsg,
                                                   const float* __restrict__ Wp,
                                                   const float* __restrict__ bp,
                                                   float* __restrict__ gmm) {
    extern __shared__ float Ws[];                   // [128][96] = [mu|sigma|pi]
    int tid = threadIdx.x;
    for (int i = tid; i < 128 * 96; i += 384) {
        int k = i / 96, c = i - k * 96;
        Ws[i] = (c < 32) ? Wm[k * 32 + c]
              : (c < 64) ? Wsg[k * 32 + (c - 32)]
                         : Wp[k * 32 + (c - 64)];
    }
    __syncthreads();

    int r = tid >> 7;                // head selector (warp-uniform)
    int p = tid & 127;
    int n0 = blockIdx.x * 256 + 2 * p;
    int n1 = n0 + 1;
    int m0 = min(n0, NN - 1), m1 = min(n1, NN - 1);

    const float* bias = (r == 0) ? bm : (r == 1) ? bsg : bp;
    ull acc0[16], acc1[16];
    init_acc(acc0, acc1, bias);
    const float* W = Ws + 32 * r;

    const float4* A0 = (const float4*)(out1 + (size_t)m0 * 128);
    const float4* A1 = (const float4*)(out1 + (size_t)m1 * 128);
#pragma unroll 2
    for (int kk = 0; kk < 32; kk++) {
        float4 a = A0[kk], b = A1[kk];
        const float* Wk = W + (4 * kk) * 96;
        step2(acc0, acc1, Wk,          a.x, b.x);
        step2(acc0, acc1, Wk + 96,     a.y, b.y);
        step2(acc0, acc1, Wk + 192,    a.z, b.z);
        step2(acc0, acc1, Wk + 288,    a.w, b.w);
    }

#pragma unroll
    for (int i = 0; i < 2; i++) {
        int gn = (i == 0) ? n0 : n1;
        if (gn >= NN) break;
        ull* acc = (i == 0) ? acc0 : acc1;
        float v[32];
#pragma unroll
        for (int j = 0; j < 16; j++) unpack2(acc[j], v[2 * j], v[2 * j + 1]);

        if (r == 1) {                  // sigma = softplus
#pragma unroll
            for (int j = 0; j < 32; j++)
                v[j] = (v[j] > 20.f) ? v[j] : log1pf(__expf(v[j]));
        } else if (r == 2) {           // pi = softmax over 32 (in-thread)
            float m = v[0];
#pragma unroll
            for (int j = 1; j < 32; j++) m = fmaxf(m, v[j]);
            float s = 0.f;
#pragma unroll
            for (int j = 0; j < 32; j++) { v[j] = __expf(v[j] - m); s += v[j]; }
            float inv = 1.f / s;
#pragma unroll
            for (int j = 0; j < 32; j++) v[j] *= inv;
        }
        float4* o = (float4*)(gmm + (size_t)gn * 96 + 32 * r);
#pragma unroll
        for (int j = 0; j < 8; j++)
            o[j] = make_float4(v[4 * j], v[4 * j + 1], v[4 * j + 2], v[4 * j + 3]);
    }
}

// ---------------- launch -------------------------------------------------------
extern "C" void kernel_launch(void* const* d_in, const int* in_sizes, int n_in,
                              void* d_out, int out_size) {
    const float* x   = (const float*)d_in[0];
    const float* xh  = (const float*)d_in[1];
    const float* h   = (const float*)d_in[2];
    const int*   ei  = (const int*)d_in[3];
    const float* ew  = (const float*)d_in[4];
    const float* Win = (const float*)d_in[5];
    const float* bin = (const float*)d_in[6];
    const float* Wf  = (const float*)d_in[7];
    const float* bf  = (const float*)d_in[8];
    const float* Wm  = (const float*)d_in[9];
    const float* bm  = (const float*)d_in[10];
    const float* Wsg = (const float*)d_in[11];
    const float* bsg = (const float*)d_in[12];
    const float* Wp  = (const float*)d_in[13];
    const float* bp  = (const float*)d_in[14];

    float* out  = (float*)d_out;
    float* gmm  = out;                          // [N, 96]
    float* out1 = out + (size_t)NN * 96;        // [N, 128]
    float* hout = out1 + (size_t)NN * 128;      // [N, 64]

    const int SMEM_HEADS = 128 * 96 * 4;        // 49152
    cudaFuncSetAttribute(k_heads2, cudaFuncAttributeMaxDynamicSharedMemorySize,
                         SMEM_HEADS);

    int nb2 = (NN + 255) / 256;   // 391 blocks, 256 nodes each

    k_zero<<<(NN / 4 + 255) / 256, 256>>>();
    k_deg<<<(EE + 255) / 256, 256>>>(ei, ew);
    k_rdeg<<<(NN + 255) / 256, 256>>>();
    k_proj4<<<nb2, 256>>>(x, xh, h, Win, bin);
    k_diff<<<(EE * 16) / 256, 256>>>(ei, ew);
    k_filt4<<<nb2, 256>>>(h, Wf, bf, out1, hout);
    k_heads2<<<nb2, 384, SMEM_HEADS>>>(out1, Wm, bm, Wsg, bsg, Wp, bp, gmm);
}